// round 13
// baseline (speedup 1.0000x reference)
#include <cuda_runtime.h>
#include <cuda_fp16.h>
#include <cstddef>

// GATNE-T fused (R13): R12 + register diet (inline half2 W1 loads, fused 4-t
// score loop), launch_bounds(256,5) for 5 CTAs/SM, explicit 20-wide gather
// load batches to preserve memory-level parallelism under the reg cap.
//
// Inputs (metadata order):
//  0 targets   int32  [B]
//  1 types     int32  [B]
//  2 neighbors int32  [B,T,S]
//  3 base_node_embeddings float [V,E]
//  4 node_type_embeddings float [V,T,D]
//  5 trans_weights    float [T,D,E]
//  6 trans_weights_s1 float [T,D,A]
//  7 trans_weights_s2 float [T,A,1]
// Output: float [B,E]

namespace {
constexpr int T = 4;
constexpr int S = 10;
constexpr int D = 32;
constexpr int E = 128;
constexpr int A = 32;
constexpr int NW = 8;          // warps per CTA
}

// fp16 weight copies (rebuilt every launch; deterministic).
__device__ __half  g_twh[T * D * E];            // [t][d][e]  (32KB)
__device__ __half2 g_tw1h2[T * (D / 2) * A];    // [t][dp][a] = (w1[2dp][a], w1[2dp+1][a])

__device__ __forceinline__ float tanh_approx(float x) {
    float y;
    asm("tanh.approx.f32 %0, %1;" : "=f"(y) : "f"(x));
    return y;
}

// ---------------------------------------------------------------------------
// K0: build fp16 weight tables (tiny).
// ---------------------------------------------------------------------------
__global__ void k_convert(const float* __restrict__ tw,
                          const float* __restrict__ tw1)
{
    const int i = blockIdx.x * blockDim.x + threadIdx.x;
    if (i < T * D * E) g_twh[i] = __float2half_rn(tw[i]);
    if (i < T * (D / 2) * A) {
        const int t  = i / ((D / 2) * A);
        const int r  = i % ((D / 2) * A);
        const int dp = r / A;
        const int a  = r % A;
        const float* p = tw1 + (size_t)t * (D * A);
        g_tw1h2[i] = __floats2half2_rn(p[(2 * dp) * A + a],
                                       p[(2 * dp + 1) * A + a]);
    }
}

// ---------------------------------------------------------------------------
// Main fused kernel: warp-per-b.
// ---------------------------------------------------------------------------
__global__ __launch_bounds__(32 * NW, 5) void gatne_warp(
    const int*   __restrict__ targets,
    const int*   __restrict__ types,
    const int*   __restrict__ neighbors,  // [B,T,S]
    const float* __restrict__ base_emb,   // [V,E]
    const float* __restrict__ nte,        // [V,T,D]
    const float* __restrict__ tw2,        // [T,A]
    float*       __restrict__ out,        // [B,E]
    int B)
{
    const int wid  = threadIdx.x >> 5;
    const int lane = threadIdx.x & 31;

    __shared__ float sh_agg[NW][T][D];
    __shared__ float sh_nat[NW][D];

    const int b = blockIdx.x * NW + wid;
    if (b >= B) return;

    const int ty  = types[b];      // broadcast LDG
    const int tgt = targets[b];    // broadcast LDG

    // PREFETCH the random base_emb gather (overlaps neighbor gathers).
    const float4 bv = __ldg((const float4*)(base_emb + (size_t)tgt * E) + lane);

    // neighbor indices: 2 coalesced loads for 40 ints
    const int* nbp = neighbors + (size_t)b * (T * S);
    const int nbv0 = nbp[lane];
    const int nbv1 = (lane < T * S - 32) ? nbp[32 + lane] : 0;

    // ---- gather + mean: two explicit 20-wide load batches (pinned MLP) ----
    float acc[T];
    {
        float r0[2 * S];
        #pragma unroll
        for (int s = 0; s < S; ++s) {     // t = 0,1 : 20 loads in flight
            const int v0 = __shfl_sync(0xffffffffu, nbv0, s);
            const int v1 = __shfl_sync(0xffffffffu, nbv0, S + s);
            r0[s]     = __ldg(&nte[(size_t)v0 * (T * D) + 0 * D + lane]);
            r0[S + s] = __ldg(&nte[(size_t)v1 * (T * D) + 1 * D + lane]);
        }
        float a0 = 0.f, a1 = 0.f;
        #pragma unroll
        for (int s = 0; s < S; ++s) { a0 += r0[s]; a1 += r0[S + s]; }

        float r1[2 * S];
        #pragma unroll
        for (int s = 0; s < S; ++s) {     // t = 2,3 : next 20 loads
            const int flat2 = 2 * S + s;  // 20..29 -> nbv0 lanes 20..29
            const int flat3 = 3 * S + s;  // 30..39 -> nbv0 30,31 then nbv1
            const int v2 = __shfl_sync(0xffffffffu, nbv0, flat2);
            const int v3 = (flat3 < 32)
                ? __shfl_sync(0xffffffffu, nbv0, flat3)
                : __shfl_sync(0xffffffffu, nbv1, flat3 - 32);
            r1[s]     = __ldg(&nte[(size_t)v2 * (T * D) + 2 * D + lane]);
            r1[S + s] = __ldg(&nte[(size_t)v3 * (T * D) + 3 * D + lane]);
        }
        float a2 = 0.f, a3 = 0.f;
        #pragma unroll
        for (int s = 0; s < S; ++s) { a2 += r1[s]; a3 += r1[S + s]; }

        acc[0] = a0 * (1.0f / (float)S);
        acc[1] = a1 * (1.0f / (float)S);
        acc[2] = a2 * (1.0f / (float)S);
        acc[3] = a3 * (1.0f / (float)S);
    }

    #pragma unroll
    for (int t = 0; t < T; ++t) sh_agg[wid][t][lane] = acc[t];
    __syncwarp();

    // ---- scores: fused 4-t loop, W1 loaded inline as half2 (shared by ts) --
    float s0 = 0.f, s1 = 0.f, s2 = 0.f, s3 = 0.f;
    float z0 = 0.f, z1 = 0.f, z2 = 0.f, z3 = 0.f;
    {
        const __half2* w1h = g_tw1h2 + (size_t)ty * ((D / 2) * A) + lane;
        const float4* ap0 = (const float4*)sh_agg[wid][0];
        const float4* ap1 = (const float4*)sh_agg[wid][1];
        const float4* ap2 = (const float4*)sh_agg[wid][2];
        const float4* ap3 = (const float4*)sh_agg[wid][3];
        #pragma unroll
        for (int q = 0; q < D / 4; ++q) {
            const float2 fa = __half22float2(__ldg(&w1h[(2 * q) * A]));
            const float2 fb = __half22float2(__ldg(&w1h[(2 * q + 1) * A]));
            const float4 v0 = ap0[q];
            const float4 v1 = ap1[q];
            const float4 v2 = ap2[q];
            const float4 v3 = ap3[q];
            s0 = fmaf(v0.x, fa.x, s0); z0 = fmaf(v0.y, fa.y, z0);
            s0 = fmaf(v0.z, fb.x, s0); z0 = fmaf(v0.w, fb.y, z0);
            s1 = fmaf(v1.x, fa.x, s1); z1 = fmaf(v1.y, fa.y, z1);
            s1 = fmaf(v1.z, fb.x, s1); z1 = fmaf(v1.w, fb.y, z1);
            s2 = fmaf(v2.x, fa.x, s2); z2 = fmaf(v2.y, fa.y, z2);
            s2 = fmaf(v2.z, fb.x, s2); z2 = fmaf(v2.w, fb.y, z2);
            s3 = fmaf(v3.x, fa.x, s3); z3 = fmaf(v3.y, fa.y, z3);
            s3 = fmaf(v3.z, fb.x, s3); z3 = fmaf(v3.w, fb.y, z3);
        }
    }
    const float tw2v = __ldg(&tw2[ty * A + lane]);
    float u0 = tanh_approx(s0 + z0) * tw2v;
    float u1 = tanh_approx(s1 + z1) * tw2v;
    float u2 = tanh_approx(s2 + z2) * tw2v;
    float u3 = tanh_approx(s3 + z3) * tw2v;

    #pragma unroll
    for (int off = 16; off > 0; off >>= 1) {
        u0 += __shfl_xor_sync(0xffffffffu, u0, off);
        u1 += __shfl_xor_sync(0xffffffffu, u1, off);
        u2 += __shfl_xor_sync(0xffffffffu, u2, off);
        u3 += __shfl_xor_sync(0xffffffffu, u3, off);
    }

    // ---- softmax over T=4 + attended embedding (lane = d) ----
    const float m  = fmaxf(fmaxf(u0, u1), fmaxf(u2, u3));
    const float e0 = __expf(u0 - m), e1 = __expf(u1 - m);
    const float e2 = __expf(u2 - m), e3 = __expf(u3 - m);
    const float inv = 1.0f / (e0 + e1 + e2 + e3);
    sh_nat[wid][lane] = (e0 * acc[0] + e1 * acc[1] +
                         e2 * acc[2] + e3 * acc[3]) * inv;
    __syncwarp();

    // ---- projection: lane owns e in [4*lane, 4*lane+4); fp16 weights ----
    const __half* wb = g_twh + (size_t)ty * (D * E) + 4 * lane;
    float4 a4 = make_float4(0.f, 0.f, 0.f, 0.f);
    float4 b4 = make_float4(0.f, 0.f, 0.f, 0.f);
    const float4* np = (const float4*)sh_nat[wid];
    #pragma unroll
    for (int q = 0; q < D / 4; ++q) {
        const float4 n4 = np[q];           // broadcast LDS.128
        #pragma unroll
        for (int j = 0; j < 4; ++j) {
            const int d = 4 * q + j;
            const float nd = (j == 0) ? n4.x : (j == 1) ? n4.y
                           : (j == 2) ? n4.z : n4.w;
            const uint2 raw = __ldg((const uint2*)(wb + d * E)); // 4 halves
            const float2 f0 = __half22float2(*(const __half2*)&raw.x);
            const float2 f1 = __half22float2(*(const __half2*)&raw.y);
            if (j & 1) {
                b4.x = fmaf(nd, f0.x, b4.x); b4.y = fmaf(nd, f0.y, b4.y);
                b4.z = fmaf(nd, f1.x, b4.z); b4.w = fmaf(nd, f1.y, b4.w);
            } else {
                a4.x = fmaf(nd, f0.x, a4.x); a4.y = fmaf(nd, f0.y, a4.y);
                a4.z = fmaf(nd, f1.x, a4.z); a4.w = fmaf(nd, f1.y, a4.w);
            }
        }
    }

    const float4 val = make_float4(a4.x + b4.x + bv.x, a4.y + b4.y + bv.y,
                                   a4.z + b4.z + bv.z, a4.w + b4.w + bv.w);

    // ---- l2 norm: warp butterfly = exact sum over all 128 outputs ----
    float ss = val.x * val.x + val.y * val.y + val.z * val.z + val.w * val.w;
    #pragma unroll
    for (int off = 16; off > 0; off >>= 1)
        ss += __shfl_xor_sync(0xffffffffu, ss, off);
    const float r = rsqrtf(fmaxf(ss, 1e-12f));

    const float4 o = make_float4(val.x * r, val.y * r, val.z * r, val.w * r);
    ((float4*)(out + (size_t)b * E))[lane] = o;
}

extern "C" void kernel_launch(void* const* d_in, const int* in_sizes, int n_in,
                              void* d_out, int out_size) {
    const int*   targets   = (const int*)  d_in[0];
    const int*   types     = (const int*)  d_in[1];
    const int*   neighbors = (const int*)  d_in[2];
    const float* base_emb  = (const float*)d_in[3];
    const float* nte       = (const float*)d_in[4];
    const float* tw        = (const float*)d_in[5];
    const float* tw1       = (const float*)d_in[6];
    const float* tw2       = (const float*)d_in[7];
    float* out = (float*)d_out;

    const int B = in_sizes[0];

    k_convert<<<(T * D * E + 255) / 256, 256>>>(tw, tw1);

    const int grid = (B + NW - 1) / NW;
    gatne_warp<<<grid, 32 * NW>>>(targets, types, neighbors,
                                  base_emb, nte, tw2, out, B);
}